// round 11
// baseline (speedup 1.0000x reference)
#include <cuda_runtime.h>
#include <cuda_fp16.h>
#include <cstdint>
#include <math.h>

#define HID 128
#define NEAR_T 0.01f
#define FAR_T 10.0f
#define MAX_IT 32
#define TILE_RAYS 32
#define NTHREADS 384
#define ASTRIDE 68
#define ACTX 2176          // words per context A buffer (32*68)
#define INV2048 4.8828125e-4f

// ---- smem layout (float-word offsets) ----
#define OFF_BPK   0        // 16384 : B frags float4 (b0h,b1h,b0l,b1l)
#define OFF_AH    16384    // 13056 : Ah, 6 contexts x 2176 words
#define OFF_AL    29440    // 13056 : Al (scaled 2048)
#define OFF_W1P   42496    // 544 : W1 interleaved, 4 kseg blocks (bank-phased)
#define OFF_WC1B  43040    // 512
#define OFF_WC2B  43552    // 512
#define OFF_BW    44064    // 256 : (b2[n], W3[n])
#define OFF_BC2   44320    // 4
#define OFF_PART  44324    // 768 : 6 contexts x part[ray*4 + ng]
#define OFF_WFRZ  45092    // 24 ints : 6 contexts x 4 warp flags
#define OFF_TILE  45116    // 6 ints
#define SMEM_WORDS 45128   // 180512 bytes -> 1 CTA/SM

__device__ int g_tile_ctr;
__global__ void reset_ctr_kernel() { g_tile_ctr = 0; }

#define BAR_W(id) asm volatile("bar.sync %0, 128;" :: "r"(id) : "memory")

__device__ __forceinline__ uint32_t h2u(__half2 h) {
    return *reinterpret_cast<uint32_t*>(&h);
}
__device__ __forceinline__ uint32_t smem_u32(const void* p) {
    uint32_t a;
    asm("{ .reg .u64 t; cvta.to.shared.u64 t, %1; cvt.u32.u64 %0, t; }" : "=r"(a) : "l"(p));
    return a;
}
__device__ __forceinline__ void mma16(float* c, const uint32_t* a,
                                      uint32_t b0, uint32_t b1) {
    asm volatile(
        "mma.sync.aligned.m16n8k16.row.col.f32.f16.f16.f32 "
        "{%0,%1,%2,%3}, {%4,%5,%6,%7}, {%8,%9}, {%0,%1,%2,%3};"
        : "+f"(c[0]), "+f"(c[1]), "+f"(c[2]), "+f"(c[3])
        : "r"(a[0]), "r"(a[1]), "r"(a[2]), "r"(a[3]), "r"(b0), "r"(b1));
}
__device__ __forceinline__ void ldsm4(uint32_t* r, uint32_t addr) {
    asm volatile("ldmatrix.sync.aligned.m8n8.x4.shared.b16 {%0,%1,%2,%3}, [%4];"
        : "=r"(r[0]), "=r"(r[1]), "=r"(r[2]), "=r"(r[3]) : "r"(addr));
}

// layer 1 for one ray, 32 k (kseg), write fp16 hi/lo
__device__ __forceinline__ void compute_h1(const float4* w1blk, uint32_t* AhW, uint32_t* AlW,
                                           int aray, int akseg,
                                           float px, float py, float pz)
{
    #pragma unroll
    for (int j = 0; j < 4; ++j) {
        uint32_t hw[4], lw[4];
        #pragma unroll
        for (int q = 0; q < 4; ++q) {
            int kpl = j * 4 + q;
            float4 q0 = w1blk[kpl * 2], q1 = w1blk[kpl * 2 + 1];
            float h0 = fmaxf(fmaf(px, q0.x, fmaf(py, q0.y, fmaf(pz, q0.z, q0.w))), 0.f);
            float h1v = fmaxf(fmaf(px, q1.x, fmaf(py, q1.y, fmaf(pz, q1.z, q1.w))), 0.f);
            __half2 hh = __floats2half2_rn(h0, h1v);
            float2 bk = __half22float2(hh);
            __half2 ll = __floats2half2_rn((h0 - bk.x) * 2048.f, (h1v - bk.y) * 2048.f);
            hw[q] = h2u(hh);
            lw[q] = h2u(ll);
        }
        int base = aray * ASTRIDE + akseg * 16 + j * 4;
        *(uint4*)(AhW + base) = make_uint4(hw[0], hw[1], hw[2], hw[3]);
        *(uint4*)(AlW + base) = make_uint4(lw[0], lw[1], lw[2], lw[3]);
    }
}

// layer 2 (fp16 3-term) + fused layer 3 partials for one context
__device__ __forceinline__ void phase_B(const float4* bbase, uint32_t ahAddr, uint32_t alAddr,
                                        const float* bw, float* part,
                                        int ng, int gid, int tig)
{
    float ch[2][4][4], cl[2][4][4];
    #pragma unroll
    for (int mh = 0; mh < 2; ++mh)
        #pragma unroll
        for (int j = 0; j < 4; ++j)
            #pragma unroll
            for (int q = 0; q < 4; ++q) { ch[mh][j][q] = 0.f; cl[mh][j][q] = 0.f; }

    #pragma unroll
    for (int ks = 0; ks < 8; ++ks) {
        float4 bv[4];
        #pragma unroll
        for (int j = 0; j < 4; ++j) bv[j] = bbase[ks * 512 + j * 32];
        uint32_t ah[2][4], al[2][4];
        ldsm4(ah[0], ahAddr + ks * 32);
        ldsm4(ah[1], ahAddr + 4352 + ks * 32);
        ldsm4(al[0], alAddr + ks * 32);
        ldsm4(al[1], alAddr + 4352 + ks * 32);
        #pragma unroll
        for (int j = 0; j < 4; ++j) {
            uint32_t b0h = __float_as_uint(bv[j].x), b1h = __float_as_uint(bv[j].y);
            mma16(ch[0][j], ah[0], b0h, b1h);
            mma16(ch[1][j], ah[1], b0h, b1h);
            mma16(cl[0][j], al[0], b0h, b1h);
            mma16(cl[1][j], al[1], b0h, b1h);
        }
        #pragma unroll
        for (int j = 0; j < 4; ++j) {
            uint32_t b0l = __float_as_uint(bv[j].z), b1l = __float_as_uint(bv[j].w);
            mma16(cl[0][j], ah[0], b0l, b1l);
            mma16(cl[1][j], ah[1], b0l, b1l);
        }
    }

    float rs[2][2] = {{0.f, 0.f}, {0.f, 0.f}};
    #pragma unroll
    for (int mh = 0; mh < 2; ++mh) {
        #pragma unroll
        for (int j = 0; j < 4; ++j) {
            const int n0 = ng * 32 + j * 8 + tig * 2;
            float4 bwv = *(const float4*)(bw + n0 * 2);
            float f0 = fmaf(cl[mh][j][0], INV2048, ch[mh][j][0]) + bwv.x;
            float f1 = fmaf(cl[mh][j][1], INV2048, ch[mh][j][1]) + bwv.z;
            float f2 = fmaf(cl[mh][j][2], INV2048, ch[mh][j][2]) + bwv.x;
            float f3 = fmaf(cl[mh][j][3], INV2048, ch[mh][j][3]) + bwv.z;
            rs[mh][0] = fmaf(fmaxf(f0, 0.f), bwv.y, rs[mh][0]);
            rs[mh][0] = fmaf(fmaxf(f1, 0.f), bwv.w, rs[mh][0]);
            rs[mh][1] = fmaf(fmaxf(f2, 0.f), bwv.y, rs[mh][1]);
            rs[mh][1] = fmaf(fmaxf(f3, 0.f), bwv.w, rs[mh][1]);
        }
    }
    #pragma unroll
    for (int off = 1; off < 4; off <<= 1) {
        rs[0][0] += __shfl_xor_sync(0xffffffffu, rs[0][0], off);
        rs[0][1] += __shfl_xor_sync(0xffffffffu, rs[0][1], off);
        rs[1][0] += __shfl_xor_sync(0xffffffffu, rs[1][0], off);
        rs[1][1] += __shfl_xor_sync(0xffffffffu, rs[1][1], off);
    }
    if (tig == 0) {
        part[(gid)      * 4 + ng] = rs[0][0];
        part[(gid + 8)  * 4 + ng] = rs[0][1];
        part[(gid + 16) * 4 + ng] = rs[1][0];
        part[(gid + 24) * 4 + ng] = rs[1][1];
    }
}

extern __shared__ float smem[];

__global__ void __launch_bounds__(NTHREADS, 1)
sphere_trace_kernel(const float* __restrict__ org,
                    const float* __restrict__ dir,
                    const float* __restrict__ W1, const float* __restrict__ b1,
                    const float* __restrict__ W2, const float* __restrict__ b2,
                    const float* __restrict__ W3, const float* __restrict__ b3,
                    const float* __restrict__ Wc1, const float* __restrict__ bc1,
                    const float* __restrict__ Wc2, const float* __restrict__ bc2,
                    float* __restrict__ out, int N, int ntiles)
{
    float4* Bpk = (float4*)(smem + OFF_BPK);
    float*  bw  = smem + OFF_BW;
    int*    wfrz = (int*)(smem + OFF_WFRZ);
    int*    stile = (int*)(smem + OFF_TILE);

    const uint32_t sb = smem_u32(smem);
    const int t    = threadIdx.x;
    const int lane = t & 31;
    const int worker = t >> 7;          // 0..2
    const int wl   = (t >> 5) & 3;      // warp-in-worker
    const int ng   = wl;
    const int gid  = lane >> 2;
    const int tig  = lane & 3;
    const int aray  = wl * 8 + (lane & 7);
    const int akseg = lane >> 3;
    const int barid = 1 + worker;
    const int slot0 = worker * 2, slot1 = slot0 + 1;

    // ---- one-time staging (whole CTA) ----
    for (int idx = t; idx < 4096; idx += NTHREADS) {
        int ln = idx & 31, jn = (idx >> 5) & 15, ks = idx >> 9;
        int n  = jn * 8 + (ln >> 2);
        int k0 = ks * 16 + 2 * (ln & 3);
        float w00 = W2[k0*HID + n],     w01 = W2[(k0+1)*HID + n];
        float w10 = W2[(k0+8)*HID + n], w11 = W2[(k0+9)*HID + n];
        __half2 bh0 = __floats2half2_rn(w00, w01);
        __half2 bh1 = __floats2half2_rn(w10, w11);
        float2 r0 = __half22float2(bh0), r1 = __half22float2(bh1);
        __half2 bl0 = __floats2half2_rn((w00 - r0.x) * 2048.f, (w01 - r0.y) * 2048.f);
        __half2 bl1 = __floats2half2_rn((w10 - r1.x) * 2048.f, (w11 - r1.y) * 2048.f);
        Bpk[idx] = make_float4(__uint_as_float(h2u(bh0)), __uint_as_float(h2u(bh1)),
                               __uint_as_float(h2u(bl0)), __uint_as_float(h2u(bl1)));
    }
    if (t < 128) {
        int kseg = t >> 5, klocal = t & 31, kpl = klocal >> 1, hh = klocal & 1;
        ((float4*)(smem + OFF_W1P))[kseg * 34 + kpl * 2 + hh] =
            make_float4(W1[t], W1[HID + t], W1[2*HID + t], b1[t]);
        float* wc1b = smem + OFF_WC1B;
        float* wc2b = smem + OFF_WC2B;
        wc1b[t*4+0] = Wc1[t];       wc1b[t*4+1] = Wc1[HID+t];
        wc1b[t*4+2] = Wc1[2*HID+t]; wc1b[t*4+3] = bc1[t];
        wc2b[t*4+0] = Wc2[3*t];     wc2b[t*4+1] = Wc2[3*t+1];
        wc2b[t*4+2] = Wc2[3*t+2];   wc2b[t*4+3] = 0.0f;
        bw[2*t]   = b2[t];
        bw[2*t+1] = W3[t];
    }
    if (t < 4) (smem + OFF_BC2)[t] = (t < 3) ? bc2[t] : 0.0f;
    const float bias3 = b3[0];

    const float4* w1blk = (const float4*)(smem + OFF_W1P) + akseg * 34;
    const float4* bbase = Bpk + ng * 128 + lane;

    uint32_t* AhW0 = (uint32_t*)(smem + OFF_AH) + slot0 * ACTX;
    uint32_t* AlW0 = (uint32_t*)(smem + OFF_AL) + slot0 * ACTX;
    uint32_t* AhW1 = AhW0 + ACTX;
    uint32_t* AlW1 = AlW0 + ACTX;
    float* part0 = smem + OFF_PART + slot0 * 128;
    float* part1 = part0 + 128;
    int* wfrz0 = wfrz + slot0 * 4;
    int* wfrz1 = wfrz0 + 4;

    const uint32_t laneoff = (uint32_t)(lane & 15) * 272 + (uint32_t)((lane >> 4) & 1) * 16;
    const uint32_t ahA0 = sb + (OFF_AH + slot0 * ACTX) * 4 + laneoff;
    const uint32_t alA0 = sb + (OFF_AL + slot0 * ACTX) * 4 + laneoff;
    const uint32_t ahA1 = ahA0 + ACTX * 4;
    const uint32_t alA1 = alA0 + ACTX * 4;

    // ---- initial steals ----
    if ((t & 127) == 0) {
        stile[slot0] = atomicAdd(&g_tile_ctr, 1);
        stile[slot1] = atomicAdd(&g_tile_ctr, 1);
    }
    __syncthreads();

    // context state (registers)
    float px0, py0, pz0, dx0, dy0, dz0, dist0 = 0.f;
    float px1, py1, pz1, dx1, dy1, dz1, dist1 = 0.f;
    bool hit0 = false, frz0 = false, hit1 = false, frz1 = false;
    int it0 = 0, it1 = 0;
    int tile0 = stile[slot0], tile1 = stile[slot1];
    bool act0 = tile0 < ntiles, act1 = tile1 < ntiles;

    if (act0) {
        int ray = tile0 * TILE_RAYS + aray; if (ray >= N) ray = N - 1;
        px0 = org[3*ray]; py0 = org[3*ray+1]; pz0 = org[3*ray+2];
        dx0 = dir[3*ray]; dy0 = dir[3*ray+1]; dz0 = dir[3*ray+2];
        compute_h1(w1blk, AhW0, AlW0, aray, akseg, px0, py0, pz0);
    }
    if (act1) {
        int ray = tile1 * TILE_RAYS + aray; if (ray >= N) ray = N - 1;
        px1 = org[3*ray]; py1 = org[3*ray+1]; pz1 = org[3*ray+2];
        dx1 = dir[3*ray]; dy1 = dir[3*ray+1]; dz1 = dir[3*ray+2];
        compute_h1(w1blk, AhW1, AlW1, aray, akseg, px1, py1, pz1);
    }
    if (lane == 0) { wfrz0[wl] = 0; wfrz1[wl] = 0; }

    const float* bc = smem + OFF_BC2;

    // ---- dual-context pipelined loop ----
    while (act0 || act1) {
        BAR_W(barid);                             // A0/A1, wfrz, stile visible

        // ===== S1: ctx0 B (or steal) =====
        bool done0 = false, done1 = false;
        if (act0) {
            int4 f = *(const int4*)wfrz0;
            done0 = ((f.x & f.y & f.z & f.w) != 0) || (it0 >= MAX_IT);
            if (!done0) phase_B(bbase, ahA0, alA0, bw, part0, ng, gid, tig);
            else if ((t & 127) == 0) stile[slot0] = atomicAdd(&g_tile_ctr, 1);
        }
        BAR_W(barid);                             // part0 / stile0 visible

        // ===== S2: ctx1 B (or steal), then ctx0 C+A (or output+refill) =====
        if (act1) {
            int4 f = *(const int4*)wfrz1;
            done1 = ((f.x & f.y & f.z & f.w) != 0) || (it1 >= MAX_IT);
            if (!done1) phase_B(bbase, ahA1, alA1, bw, part1, ng, gid, tig);
            else if ((t & 127) == 0) stile[slot1] = atomicAdd(&g_tile_ctr, 1);
        }
        if (act0) {
            if (!done0) {
                float s = part0[aray * 4 + akseg];
                s += __shfl_xor_sync(0xffffffffu, s, 8);
                s += __shfl_xor_sync(0xffffffffu, s, 16);
                float sdf = bias3 + s;
                if (!frz0) {
                    const bool valid = (sdf <= NEAR_T) && (dist0 < FAR_T);
                    hit0 = hit0 || valid;
                    if (valid) frz0 = true;
                    else {
                        dist0 += sdf;
                        px0 = fmaf(dx0, sdf, px0);
                        py0 = fmaf(dy0, sdf, py0);
                        pz0 = fmaf(dz0, sdf, pz0);
                        compute_h1(w1blk, AhW0, AlW0, aray, akseg, px0, py0, pz0);
                    }
                }
                unsigned bal = __ballot_sync(0xffffffffu, frz0);
                if (lane == 0) wfrz0[wl] = (bal == 0xffffffffu) ? 1 : 0;
                ++it0;
            } else {
                // output finished tile
                {
                    float c0 = 0.f, c1 = 0.f, c2 = 0.f;
                    const float4* wc1b = (const float4*)(smem + OFF_WC1B) + akseg * 32;
                    const float4* wc2b = (const float4*)(smem + OFF_WC2B) + akseg * 32;
                    #pragma unroll 4
                    for (int j = 0; j < 32; ++j) {
                        float4 q = wc1b[j], wv = wc2b[j];
                        float h = fmaxf(fmaf(px0, q.x, fmaf(py0, q.y, fmaf(pz0, q.z, q.w))), 0.f);
                        c0 = fmaf(h, wv.x, c0); c1 = fmaf(h, wv.y, c1); c2 = fmaf(h, wv.z, c2);
                    }
                    c0 += __shfl_xor_sync(0xffffffffu, c0, 8);
                    c1 += __shfl_xor_sync(0xffffffffu, c1, 8);
                    c2 += __shfl_xor_sync(0xffffffffu, c2, 8);
                    c0 += __shfl_xor_sync(0xffffffffu, c0, 16);
                    c1 += __shfl_xor_sync(0xffffffffu, c1, 16);
                    c2 += __shfl_xor_sync(0xffffffffu, c2, 16);
                    int oray = tile0 * TILE_RAYS + aray;
                    if (lane < 8 && oray < N) {
                        const bool mask = hit0 || (dist0 < FAR_T);
                        c0 += bc[0]; c1 += bc[1]; c2 += bc[2];
                        out[3*oray]   = mask ? (1.0f / (1.0f + expf(-c0))) : 0.0f;
                        out[3*oray+1] = mask ? (1.0f / (1.0f + expf(-c1))) : 0.0f;
                        out[3*oray+2] = mask ? (1.0f / (1.0f + expf(-c2))) : 0.0f;
                    }
                }
                // refill
                tile0 = stile[slot0];
                if (tile0 < ntiles) {
                    int ray = tile0 * TILE_RAYS + aray; if (ray >= N) ray = N - 1;
                    px0 = org[3*ray]; py0 = org[3*ray+1]; pz0 = org[3*ray+2];
                    dx0 = dir[3*ray]; dy0 = dir[3*ray+1]; dz0 = dir[3*ray+2];
                    dist0 = 0.f; hit0 = false; frz0 = false; it0 = 0;
                    compute_h1(w1blk, AhW0, AlW0, aray, akseg, px0, py0, pz0);
                    if (lane == 0) wfrz0[wl] = 0;
                } else act0 = false;
            }
        }
        BAR_W(barid);                             // part1 / stile1 / wfrz0 visible

        // ===== S3: ctx1 C+A (or output+refill) =====
        if (act1) {
            if (!done1) {
                float s = part1[aray * 4 + akseg];
                s += __shfl_xor_sync(0xffffffffu, s, 8);
                s += __shfl_xor_sync(0xffffffffu, s, 16);
                float sdf = bias3 + s;
                if (!frz1) {
                    const bool valid = (sdf <= NEAR_T) && (dist1 < FAR_T);
                    hit1 = hit1 || valid;
                    if (valid) frz1 = true;
                    else {
                        dist1 += sdf;
                        px1 = fmaf(dx1, sdf, px1);
                        py1 = fmaf(dy1, sdf, py1);
                        pz1 = fmaf(dz1, sdf, pz1);
                        compute_h1(w1blk, AhW1, AlW1, aray, akseg, px1, py1, pz1);
                    }
                }
                unsigned bal = __ballot_sync(0xffffffffu, frz1);
                if (lane == 0) wfrz1[wl] = (bal == 0xffffffffu) ? 1 : 0;
                ++it1;
            } else {
                {
                    float c0 = 0.f, c1 = 0.f, c2 = 0.f;
                    const float4* wc1b = (const float4*)(smem + OFF_WC1B) + akseg * 32;
                    const float4* wc2b = (const float4*)(smem + OFF_WC2B) + akseg * 32;
                    #pragma unroll 4
                    for (int j = 0; j < 32; ++j) {
                        float4 q = wc1b[j], wv = wc2b[j];
                        float h = fmaxf(fmaf(px1, q.x, fmaf(py1, q.y, fmaf(pz1, q.z, q.w))), 0.f);
                        c0 = fmaf(h, wv.x, c0); c1 = fmaf(h, wv.y, c1); c2 = fmaf(h, wv.z, c2);
                    }
                    c0 += __shfl_xor_sync(0xffffffffu, c0, 8);
                    c1 += __shfl_xor_sync(0xffffffffu, c1, 8);
                    c2 += __shfl_xor_sync(0xffffffffu, c2, 8);
                    c0 += __shfl_xor_sync(0xffffffffu, c0, 16);
                    c1 += __shfl_xor_sync(0xffffffffu, c1, 16);
                    c2 += __shfl_xor_sync(0xffffffffu, c2, 16);
                    int oray = tile1 * TILE_RAYS + aray;
                    if (lane < 8 && oray < N) {
                        const bool mask = hit1 || (dist1 < FAR_T);
                        c0 += bc[0]; c1 += bc[1]; c2 += bc[2];
                        out[3*oray]   = mask ? (1.0f / (1.0f + expf(-c0))) : 0.0f;
                        out[3*oray+1] = mask ? (1.0f / (1.0f + expf(-c1))) : 0.0f;
                        out[3*oray+2] = mask ? (1.0f / (1.0f + expf(-c2))) : 0.0f;
                    }
                }
                tile1 = stile[slot1];
                if (tile1 < ntiles) {
                    int ray = tile1 * TILE_RAYS + aray; if (ray >= N) ray = N - 1;
                    px1 = org[3*ray]; py1 = org[3*ray+1]; pz1 = org[3*ray+2];
                    dx1 = dir[3*ray]; dy1 = dir[3*ray+1]; dz1 = dir[3*ray+2];
                    dist1 = 0.f; hit1 = false; frz1 = false; it1 = 0;
                    compute_h1(w1blk, AhW1, AlW1, aray, akseg, px1, py1, pz1);
                    if (lane == 0) wfrz1[wl] = 0;
                } else act1 = false;
            }
        }
    }
}

extern "C" void kernel_launch(void* const* d_in, const int* in_sizes, int n_in,
                              void* d_out, int out_size)
{
    const float* org = (const float*)d_in[0];
    const float* dir = (const float*)d_in[1];
    const float* W1  = (const float*)d_in[2];
    const float* b1  = (const float*)d_in[3];
    const float* W2  = (const float*)d_in[4];
    const float* b2  = (const float*)d_in[5];
    const float* W3  = (const float*)d_in[6];
    const float* b3  = (const float*)d_in[7];
    const float* Wc1 = (const float*)d_in[8];
    const float* bc1 = (const float*)d_in[9];
    const float* Wc2 = (const float*)d_in[10];
    const float* bc2 = (const float*)d_in[11];
    float* out = (float*)d_out;

    const int N = in_sizes[0] / 3;
    const int ntiles = (N + TILE_RAYS - 1) / TILE_RAYS;
    const int smem_bytes = SMEM_WORDS * sizeof(float);

    cudaFuncSetAttribute(sphere_trace_kernel,
                         cudaFuncAttributeMaxDynamicSharedMemorySize, smem_bytes);

    reset_ctr_kernel<<<1, 1>>>();

    int nblocks = 152;                 // 1 persistent CTA/SM, 3 workers x 2 contexts
    sphere_trace_kernel<<<nblocks, NTHREADS, smem_bytes>>>(
        org, dir, W1, b1, W2, b2, W3, b3, Wc1, bc1, Wc2, bc2, out, N, ntiles);
}

// round 13
// speedup vs baseline: 1.0980x; 1.0980x over previous
#include <cuda_runtime.h>
#include <cuda_fp16.h>
#include <cstdint>
#include <math.h>

#define HID 128
#define NEAR_T 0.01f
#define FAR_T 10.0f
#define MAX_IT 32
#define TILE_RAYS 32        // per half-CTA worker
#define NTHREADS 256
#define ASTRIDE 68
#define AHALF 2176          // words per half A buffer (32*68)
#define INV2048 4.8828125e-4f

// ---- smem layout (float-word offsets) ----
#define OFF_BPK   0        // 16384 : B frags float4 (b0h,b1h,b0l,b1l)
#define OFF_AH    16384    // 4352 : Ah, 2 halves x 2176 words
#define OFF_AL    20736    // 4352 : Al (scaled 2048)
#define OFF_W1P   25088    // 544 : W1 interleaved, 4 kseg blocks (bank-phased)
#define OFF_WC1B  25632    // 512
#define OFF_WC2B  26144    // 512
#define OFF_BW    26656    // 256 : (b2[n], W3[n])
#define OFF_BC2   26912    // 4
#define OFF_PART  26916    // 256 : 2 halves x part[ray*4 + ng]
#define OFF_WFRZ  27172    // 8 ints : 2 halves x 4 warp flags
#define OFF_TILE  27180    // 2 ints
#define SMEM_WORDS 27184   // 108736 bytes -> 2 CTAs/SM

__device__ int g_tile_ctr;
__global__ void reset_ctr_kernel() { g_tile_ctr = 0; }

#define BAR_HALF(id) asm volatile("bar.sync %0, 128;" :: "r"(id) : "memory")

__device__ __forceinline__ uint32_t h2u(__half2 h) {
    return *reinterpret_cast<uint32_t*>(&h);
}
__device__ __forceinline__ uint32_t smem_u32(const void* p) {
    uint32_t a;
    asm("{ .reg .u64 t; cvta.to.shared.u64 t, %1; cvt.u32.u64 %0, t; }" : "=r"(a) : "l"(p));
    return a;
}
__device__ __forceinline__ void mma16(float* c, const uint32_t* a,
                                      uint32_t b0, uint32_t b1) {
    asm volatile(
        "mma.sync.aligned.m16n8k16.row.col.f32.f16.f16.f32 "
        "{%0,%1,%2,%3}, {%4,%5,%6,%7}, {%8,%9}, {%0,%1,%2,%3};"
        : "+f"(c[0]), "+f"(c[1]), "+f"(c[2]), "+f"(c[3])
        : "r"(a[0]), "r"(a[1]), "r"(a[2]), "r"(a[3]), "r"(b0), "r"(b1));
}
__device__ __forceinline__ void ldsm4(uint32_t* r, uint32_t addr) {
    asm volatile("ldmatrix.sync.aligned.m8n8.x4.shared.b16 {%0,%1,%2,%3}, [%4];"
        : "=r"(r[0]), "=r"(r[1]), "=r"(r[2]), "=r"(r[3]) : "r"(addr));
}

// layer 1 for one ray, 32 k (kseg), write fp16 hi/lo to Ah/Al (half-local)
__device__ __forceinline__ void compute_h1(const float4* w1blk, uint32_t* AhW, uint32_t* AlW,
                                           int aray, int akseg,
                                           float px, float py, float pz)
{
    #pragma unroll
    for (int j = 0; j < 4; ++j) {
        uint32_t hw[4], lw[4];
        #pragma unroll
        for (int q = 0; q < 4; ++q) {
            int kpl = j * 4 + q;
            float4 q0 = w1blk[kpl * 2], q1 = w1blk[kpl * 2 + 1];
            float h0 = fmaxf(fmaf(px, q0.x, fmaf(py, q0.y, fmaf(pz, q0.z, q0.w))), 0.f);
            float h1v = fmaxf(fmaf(px, q1.x, fmaf(py, q1.y, fmaf(pz, q1.z, q1.w))), 0.f);
            __half2 hh = __floats2half2_rn(h0, h1v);
            float2 bk = __half22float2(hh);
            __half2 ll = __floats2half2_rn((h0 - bk.x) * 2048.f, (h1v - bk.y) * 2048.f);
            hw[q] = h2u(hh);
            lw[q] = h2u(ll);
        }
        int base = aray * ASTRIDE + akseg * 16 + j * 4;
        *(uint4*)(AhW + base) = make_uint4(hw[0], hw[1], hw[2], hw[3]);
        *(uint4*)(AlW + base) = make_uint4(lw[0], lw[1], lw[2], lw[3]);
    }
}

// phase B for a single M16 half (rowoff = 0 or 16)
__device__ __forceinline__ void phaseB_one(const float4* bbase, uint32_t ahA, uint32_t alA,
                                           const float* bw, float* part,
                                           int ng, int gid, int tig, int rowoff)
{
    float ch[4][4], cl[4][4];
    #pragma unroll
    for (int j = 0; j < 4; ++j)
        #pragma unroll
        for (int q = 0; q < 4; ++q) { ch[j][q] = 0.f; cl[j][q] = 0.f; }

    #pragma unroll
    for (int ks = 0; ks < 8; ++ks) {
        float4 bv[4];
        #pragma unroll
        for (int j = 0; j < 4; ++j) bv[j] = bbase[ks * 512 + j * 32];
        uint32_t ah[4], al[4];
        ldsm4(ah, ahA + ks * 32);
        ldsm4(al, alA + ks * 32);
        #pragma unroll
        for (int j = 0; j < 4; ++j) {
            uint32_t b0h = __float_as_uint(bv[j].x), b1h = __float_as_uint(bv[j].y);
            mma16(ch[j], ah, b0h, b1h);
            mma16(cl[j], al, b0h, b1h);
        }
        #pragma unroll
        for (int j = 0; j < 4; ++j) {
            uint32_t b0l = __float_as_uint(bv[j].z), b1l = __float_as_uint(bv[j].w);
            mma16(cl[j], ah, b0l, b1l);
        }
    }

    float rs0 = 0.f, rs1 = 0.f;
    #pragma unroll
    for (int j = 0; j < 4; ++j) {
        const int n0 = ng * 32 + j * 8 + tig * 2;
        float4 bwv = *(const float4*)(bw + n0 * 2);
        float f0 = fmaf(cl[j][0], INV2048, ch[j][0]) + bwv.x;
        float f1 = fmaf(cl[j][1], INV2048, ch[j][1]) + bwv.z;
        float f2 = fmaf(cl[j][2], INV2048, ch[j][2]) + bwv.x;
        float f3 = fmaf(cl[j][3], INV2048, ch[j][3]) + bwv.z;
        rs0 = fmaf(fmaxf(f0, 0.f), bwv.y, rs0);
        rs0 = fmaf(fmaxf(f1, 0.f), bwv.w, rs0);
        rs1 = fmaf(fmaxf(f2, 0.f), bwv.y, rs1);
        rs1 = fmaf(fmaxf(f3, 0.f), bwv.w, rs1);
    }
    #pragma unroll
    for (int off = 1; off < 4; off <<= 1) {
        rs0 += __shfl_xor_sync(0xffffffffu, rs0, off);
        rs1 += __shfl_xor_sync(0xffffffffu, rs1, off);
    }
    if (tig == 0) {
        part[(gid + rowoff)     * 4 + ng] = rs0;
        part[(gid + rowoff + 8) * 4 + ng] = rs1;
    }
}

// phase B, both halves (full M32) — identical math to R10
__device__ __forceinline__ void phaseB_full(const float4* bbase, uint32_t ahA, uint32_t alA,
                                            const float* bw, float* part,
                                            int ng, int gid, int tig)
{
    float ch[2][4][4], cl[2][4][4];
    #pragma unroll
    for (int mh = 0; mh < 2; ++mh)
        #pragma unroll
        for (int j = 0; j < 4; ++j)
            #pragma unroll
            for (int q = 0; q < 4; ++q) { ch[mh][j][q] = 0.f; cl[mh][j][q] = 0.f; }

    #pragma unroll
    for (int ks = 0; ks < 8; ++ks) {
        float4 bv[4];
        #pragma unroll
        for (int j = 0; j < 4; ++j) bv[j] = bbase[ks * 512 + j * 32];
        uint32_t ah[2][4], al[2][4];
        ldsm4(ah[0], ahA + ks * 32);
        ldsm4(ah[1], ahA + 4352 + ks * 32);
        ldsm4(al[0], alA + ks * 32);
        ldsm4(al[1], alA + 4352 + ks * 32);
        #pragma unroll
        for (int j = 0; j < 4; ++j) {
            uint32_t b0h = __float_as_uint(bv[j].x), b1h = __float_as_uint(bv[j].y);
            mma16(ch[0][j], ah[0], b0h, b1h);
            mma16(ch[1][j], ah[1], b0h, b1h);
            mma16(cl[0][j], al[0], b0h, b1h);
            mma16(cl[1][j], al[1], b0h, b1h);
        }
        #pragma unroll
        for (int j = 0; j < 4; ++j) {
            uint32_t b0l = __float_as_uint(bv[j].z), b1l = __float_as_uint(bv[j].w);
            mma16(cl[0][j], ah[0], b0l, b1l);
            mma16(cl[1][j], ah[1], b0l, b1l);
        }
    }

    float rs[2][2] = {{0.f, 0.f}, {0.f, 0.f}};
    #pragma unroll
    for (int mh = 0; mh < 2; ++mh) {
        #pragma unroll
        for (int j = 0; j < 4; ++j) {
            const int n0 = ng * 32 + j * 8 + tig * 2;
            float4 bwv = *(const float4*)(bw + n0 * 2);
            float f0 = fmaf(cl[mh][j][0], INV2048, ch[mh][j][0]) + bwv.x;
            float f1 = fmaf(cl[mh][j][1], INV2048, ch[mh][j][1]) + bwv.z;
            float f2 = fmaf(cl[mh][j][2], INV2048, ch[mh][j][2]) + bwv.x;
            float f3 = fmaf(cl[mh][j][3], INV2048, ch[mh][j][3]) + bwv.z;
            rs[mh][0] = fmaf(fmaxf(f0, 0.f), bwv.y, rs[mh][0]);
            rs[mh][0] = fmaf(fmaxf(f1, 0.f), bwv.w, rs[mh][0]);
            rs[mh][1] = fmaf(fmaxf(f2, 0.f), bwv.y, rs[mh][1]);
            rs[mh][1] = fmaf(fmaxf(f3, 0.f), bwv.w, rs[mh][1]);
        }
    }
    #pragma unroll
    for (int off = 1; off < 4; off <<= 1) {
        rs[0][0] += __shfl_xor_sync(0xffffffffu, rs[0][0], off);
        rs[0][1] += __shfl_xor_sync(0xffffffffu, rs[0][1], off);
        rs[1][0] += __shfl_xor_sync(0xffffffffu, rs[1][0], off);
        rs[1][1] += __shfl_xor_sync(0xffffffffu, rs[1][1], off);
    }
    if (tig == 0) {
        part[(gid)      * 4 + ng] = rs[0][0];
        part[(gid + 8)  * 4 + ng] = rs[0][1];
        part[(gid + 16) * 4 + ng] = rs[1][0];
        part[(gid + 24) * 4 + ng] = rs[1][1];
    }
}

extern __shared__ float smem[];

__global__ void __launch_bounds__(NTHREADS, 2)
sphere_trace_kernel(const float* __restrict__ org,
                    const float* __restrict__ dir,
                    const float* __restrict__ W1, const float* __restrict__ b1,
                    const float* __restrict__ W2, const float* __restrict__ b2,
                    const float* __restrict__ W3, const float* __restrict__ b3,
                    const float* __restrict__ Wc1, const float* __restrict__ bc1,
                    const float* __restrict__ Wc2, const float* __restrict__ bc2,
                    float* __restrict__ out, int N, int ntiles)
{
    float4* Bpk = (float4*)(smem + OFF_BPK);
    float*  bw  = smem + OFF_BW;
    int*    wfrz = (int*)(smem + OFF_WFRZ);
    int*    stile = (int*)(smem + OFF_TILE);

    const uint32_t sb = smem_u32(smem);
    const int t    = threadIdx.x;
    const int lane = t & 31;
    const int w    = t >> 5;
    const int half = t >> 7;            // 0 or 1 : independent worker
    const int wl   = w & 3;             // warp-in-half 0..3
    const int ng   = wl;                // N group : outs [ng*32, ng*32+32)
    const int gid  = lane >> 2;
    const int tig  = lane & 3;
    const int aray  = wl * 8 + (lane & 7);   // 0..31 half-local ray
    const int akseg = lane >> 3;             // 0..3
    const int barid = 1 + half;

    uint32_t* AhW = (uint32_t*)(smem + OFF_AH) + half * AHALF;
    uint32_t* AlW = (uint32_t*)(smem + OFF_AL) + half * AHALF;
    float*    part = smem + OFF_PART + half * 128;
    int*      wfrzH = wfrz + half * 4;

    // ---- one-time staging (whole CTA) ----
    for (int idx = t; idx < 4096; idx += NTHREADS) {
        int ln = idx & 31, jn = (idx >> 5) & 15, ks = idx >> 9;
        int n  = jn * 8 + (ln >> 2);
        int k0 = ks * 16 + 2 * (ln & 3);
        float w00 = W2[k0*HID + n],     w01 = W2[(k0+1)*HID + n];
        float w10 = W2[(k0+8)*HID + n], w11 = W2[(k0+9)*HID + n];
        __half2 bh0 = __floats2half2_rn(w00, w01);
        __half2 bh1 = __floats2half2_rn(w10, w11);
        float2 r0 = __half22float2(bh0), r1 = __half22float2(bh1);
        __half2 bl0 = __floats2half2_rn((w00 - r0.x) * 2048.f, (w01 - r0.y) * 2048.f);
        __half2 bl1 = __floats2half2_rn((w10 - r1.x) * 2048.f, (w11 - r1.y) * 2048.f);
        Bpk[idx] = make_float4(__uint_as_float(h2u(bh0)), __uint_as_float(h2u(bh1)),
                               __uint_as_float(h2u(bl0)), __uint_as_float(h2u(bl1)));
    }
    if (t < 128) {
        int kseg = t >> 5, klocal = t & 31, kpl = klocal >> 1, hh = klocal & 1;
        ((float4*)(smem + OFF_W1P))[kseg * 34 + kpl * 2 + hh] =
            make_float4(W1[t], W1[HID + t], W1[2*HID + t], b1[t]);
        float* wc1b = smem + OFF_WC1B;
        float* wc2b = smem + OFF_WC2B;
        wc1b[t*4+0] = Wc1[t];       wc1b[t*4+1] = Wc1[HID+t];
        wc1b[t*4+2] = Wc1[2*HID+t]; wc1b[t*4+3] = bc1[t];
        wc2b[t*4+0] = Wc2[3*t];     wc2b[t*4+1] = Wc2[3*t+1];
        wc2b[t*4+2] = Wc2[3*t+2];   wc2b[t*4+3] = 0.0f;
        bw[2*t]   = b2[t];
        bw[2*t+1] = W3[t];
    }
    if (t < 4) (smem + OFF_BC2)[t] = (t < 3) ? bc2[t] : 0.0f;
    const float bias3 = b3[0];
    __syncthreads();                  // last CTA-wide barrier

    const float4* w1blk = (const float4*)(smem + OFF_W1P) + akseg * 34;

    // ldmatrix lane base addresses (half-local A, mh=0 base)
    const uint32_t ahAddr = sb + (OFF_AH + half * AHALF) * 4
                          + (uint32_t)(lane & 15) * 272
                          + (uint32_t)((lane >> 4) & 1) * 16;
    const uint32_t alAddr = ahAddr + (OFF_AL - OFF_AH) * 4;

    // B fragment base pointer
    const float4* bbase = Bpk + ng * 128 + lane;

    // ---- persistent per-half tile loop ----
    for (;;) {
        if ((t & 127) == 0) stile[half] = atomicAdd(&g_tile_ctr, 1);
        if (lane == 0) wfrzH[wl] = 0;
        BAR_HALF(barid);
        const int tile = stile[half];
        if (tile >= ntiles) break;
        const int rbase = tile * TILE_RAYS;

        int ray = rbase + aray;
        if (ray >= N) ray = N - 1;
        float px = org[3*ray], py = org[3*ray + 1], pz = org[3*ray + 2];
        const float dx = dir[3*ray], dy = dir[3*ray + 1], dz = dir[3*ray + 2];
        float dist = 0.f;
        bool hit = false, frozen = false;

        // A0: layer 1 at origins
        compute_h1(w1blk, AhW, AlW, aray, akseg, px, py, pz);

        for (int it = 0; it < MAX_IT; ++it) {
            BAR_HALF(barid);          // A writes + wfrz visible
            int4 f4 = *(const int4*)wfrzH;
            const bool act0 = !(f4.x & f4.y);    // rays [0,16)  (warps 0,1)
            const bool act1 = !(f4.z & f4.w);    // rays [16,32) (warps 2,3)
            if (!act0 && !act1) break;

            // ===== phase B: skip fully-frozen M16 halves =====
            if (act0 && act1)
                phaseB_full(bbase, ahAddr, alAddr, bw, part, ng, gid, tig);
            else if (act0)
                phaseB_one(bbase, ahAddr, alAddr, bw, part, ng, gid, tig, 0);
            else
                phaseB_one(bbase, ahAddr + 4352, alAddr + 4352, bw, part, ng, gid, tig, 16);
            BAR_HALF(barid);          // part visible

            // ===== fused phase C+A: march update in regs, then layer 1 =====
            {
                float s = part[aray * 4 + akseg];
                s += __shfl_xor_sync(0xffffffffu, s, 8);
                s += __shfl_xor_sync(0xffffffffu, s, 16);
                float sdf = bias3 + s;
                if (!frozen) {
                    const bool valid = (sdf <= NEAR_T) && (dist < FAR_T);
                    hit = hit || valid;
                    if (valid) {
                        frozen = true;
                    } else {
                        dist += sdf;
                        px = fmaf(dx, sdf, px);
                        py = fmaf(dy, sdf, py);
                        pz = fmaf(dz, sdf, pz);
                        compute_h1(w1blk, AhW, AlW, aray, akseg, px, py, pz);
                    }
                }
                unsigned bal = __ballot_sync(0xffffffffu, frozen);
                if (lane == 0) wfrzH[wl] = (bal == 0xffffffffu) ? 1 : 0;
            }
        }

        // ===== color MLP: distributed over the 4 handler lanes per ray =====
        {
            const float* bc = smem + OFF_BC2;
            float c0 = 0.f, c1 = 0.f, c2 = 0.f;
            const float4* wc1b = (const float4*)(smem + OFF_WC1B) + akseg * 32;
            const float4* wc2b = (const float4*)(smem + OFF_WC2B) + akseg * 32;
            #pragma unroll 4
            for (int j = 0; j < 32; ++j) {
                float4 q  = wc1b[j];
                float4 wv = wc2b[j];
                float h = fmaf(px, q.x, fmaf(py, q.y, fmaf(pz, q.z, q.w)));
                h = fmaxf(h, 0.0f);
                c0 = fmaf(h, wv.x, c0);
                c1 = fmaf(h, wv.y, c1);
                c2 = fmaf(h, wv.z, c2);
            }
            c0 += __shfl_xor_sync(0xffffffffu, c0, 8);
            c1 += __shfl_xor_sync(0xffffffffu, c1, 8);
            c2 += __shfl_xor_sync(0xffffffffu, c2, 8);
            c0 += __shfl_xor_sync(0xffffffffu, c0, 16);
            c1 += __shfl_xor_sync(0xffffffffu, c1, 16);
            c2 += __shfl_xor_sync(0xffffffffu, c2, 16);
            if (lane < 8 && (rbase + aray) < N) {
                const bool mask = hit || (dist < FAR_T);
                c0 += bc[0]; c1 += bc[1]; c2 += bc[2];
                const int oray = rbase + aray;
                out[3*oray]     = mask ? (1.0f / (1.0f + expf(-c0))) : 0.0f;
                out[3*oray + 1] = mask ? (1.0f / (1.0f + expf(-c1))) : 0.0f;
                out[3*oray + 2] = mask ? (1.0f / (1.0f + expf(-c2))) : 0.0f;
            }
        }
        // loop-top barrier orders Ah/part reuse across tiles
    }
}

extern "C" void kernel_launch(void* const* d_in, const int* in_sizes, int n_in,
                              void* d_out, int out_size)
{
    const float* org = (const float*)d_in[0];
    const float* dir = (const float*)d_in[1];
    const float* W1  = (const float*)d_in[2];
    const float* b1  = (const float*)d_in[3];
    const float* W2  = (const float*)d_in[4];
    const float* b2  = (const float*)d_in[5];
    const float* W3  = (const float*)d_in[6];
    const float* b3  = (const float*)d_in[7];
    const float* Wc1 = (const float*)d_in[8];
    const float* bc1 = (const float*)d_in[9];
    const float* Wc2 = (const float*)d_in[10];
    const float* bc2 = (const float*)d_in[11];
    float* out = (float*)d_out;

    const int N = in_sizes[0] / 3;
    const int ntiles = (N + TILE_RAYS - 1) / TILE_RAYS;
    const int smem_bytes = SMEM_WORDS * sizeof(float);

    cudaFuncSetAttribute(sphere_trace_kernel,
                         cudaFuncAttributeMaxDynamicSharedMemorySize, smem_bytes);

    reset_ctr_kernel<<<1, 1>>>();

    int nblocks = 304;                 // 2 persistent CTAs per SM, 2 workers each
    sphere_trace_kernel<<<nblocks, NTHREADS, smem_bytes>>>(
        org, dir, W1, b1, W2, b2, W3, b3, Wc1, bc1, Wc2, bc2, out, N, ntiles);
}

// round 14
// speedup vs baseline: 1.2037x; 1.0963x over previous
#include <cuda_runtime.h>
#include <cuda_fp16.h>
#include <cstdint>
#include <math.h>

#define HID 128
#define NEAR_T 0.01f
#define FAR_T 10.0f
#define MAX_IT 32
#define TILE_RAYS 32        // per worker (2 warps)
#define NTHREADS 512
#define ASTRIDE 68
#define AWORK 2176          // words per worker A buffer (32*68)

// ---- smem layout (float-word offsets) ----
#define OFF_BPK   0        // 16384 : B frags float4 (b0h,b1h,b0l,b1l)
#define OFF_AH    16384    // 17408 : Ah, 8 workers x 2176 words
#define OFF_AL    33792    // 17408 : Al (UNSCALED residual)
#define OFF_W1P   51200    // 544 : W1 interleaved, 4 kseg blocks
#define OFF_WC1B  51744    // 512
#define OFF_WC2B  52256    // 512
#define OFF_BW    52768    // 256 : (b2[n], W3[n])
#define OFF_BC2   53024    // 4
#define OFF_SCR   53028    // 2048 : 8 workers x 256 (part[ray*2+ng] @0, color partials @64)
#define OFF_TILE  55076    // 8 ints
#define SMEM_WORDS 55088   // 220352 bytes -> 1 CTA/SM

__device__ int g_tile_ctr;
__global__ void reset_ctr_kernel() { g_tile_ctr = 0; }

#define BAR_W(id) asm volatile("bar.sync %0, 64;" :: "r"(id) : "memory")

__device__ __forceinline__ uint32_t h2u(__half2 h) {
    return *reinterpret_cast<uint32_t*>(&h);
}
__device__ __forceinline__ uint32_t smem_u32(const void* p) {
    uint32_t a;
    asm("{ .reg .u64 t; cvta.to.shared.u64 t, %1; cvt.u32.u64 %0, t; }" : "=r"(a) : "l"(p));
    return a;
}
__device__ __forceinline__ void mma16(float* c, const uint32_t* a,
                                      uint32_t b0, uint32_t b1) {
    asm volatile(
        "mma.sync.aligned.m16n8k16.row.col.f32.f16.f16.f32 "
        "{%0,%1,%2,%3}, {%4,%5,%6,%7}, {%8,%9}, {%0,%1,%2,%3};"
        : "+f"(c[0]), "+f"(c[1]), "+f"(c[2]), "+f"(c[3])
        : "r"(a[0]), "r"(a[1]), "r"(a[2]), "r"(a[3]), "r"(b0), "r"(b1));
}
__device__ __forceinline__ void ldsm4(uint32_t* r, uint32_t addr) {
    asm volatile("ldmatrix.sync.aligned.m8n8.x4.shared.b16 {%0,%1,%2,%3}, [%4];"
        : "=r"(r[0]), "=r"(r[1]), "=r"(r[2]), "=r"(r[3]) : "r"(addr));
}

// layer 1 for one ray, 64 k (2 ksegs selected by ng), fp16 hi + UNSCALED lo
__device__ __forceinline__ void compute_h1(const float4* w1p, uint32_t* AhW, uint32_t* AlW,
                                           int ray, int ng,
                                           float px, float py, float pz)
{
    #pragma unroll
    for (int seg = 0; seg < 2; ++seg) {
        const float4* blk = w1p + (2 * ng + seg) * 34;
        #pragma unroll
        for (int j = 0; j < 4; ++j) {
            uint32_t hw[4], lw[4];
            #pragma unroll
            for (int q = 0; q < 4; ++q) {
                int kpl = j * 4 + q;
                float4 q0 = blk[kpl * 2], q1 = blk[kpl * 2 + 1];
                float h0 = fmaxf(fmaf(px, q0.x, fmaf(py, q0.y, fmaf(pz, q0.z, q0.w))), 0.f);
                float h1v = fmaxf(fmaf(px, q1.x, fmaf(py, q1.y, fmaf(pz, q1.z, q1.w))), 0.f);
                __half2 hh = __floats2half2_rn(h0, h1v);
                float2 bk = __half22float2(hh);
                __half2 ll = __floats2half2_rn(h0 - bk.x, h1v - bk.y);   // unscaled residual
                hw[q] = h2u(hh);
                lw[q] = h2u(ll);
            }
            int base = ray * ASTRIDE + (2 * ng + seg) * 16 + j * 4;
            *(uint4*)(AhW + base) = make_uint4(hw[0], hw[1], hw[2], hw[3]);
            *(uint4*)(AlW + base) = make_uint4(lw[0], lw[1], lw[2], lw[3]);
        }
    }
}

extern __shared__ float smem[];

__global__ void __launch_bounds__(NTHREADS, 1)
sphere_trace_kernel(const float* __restrict__ org,
                    const float* __restrict__ dir,
                    const float* __restrict__ W1, const float* __restrict__ b1,
                    const float* __restrict__ W2, const float* __restrict__ b2,
                    const float* __restrict__ W3, const float* __restrict__ b3,
                    const float* __restrict__ Wc1, const float* __restrict__ bc1,
                    const float* __restrict__ Wc2, const float* __restrict__ bc2,
                    float* __restrict__ out, int N, int ntiles)
{
    float4* Bpk = (float4*)(smem + OFF_BPK);
    float*  bw  = smem + OFF_BW;
    int*    stile = (int*)(smem + OFF_TILE);

    const uint32_t sb = smem_u32(smem);
    const int t      = threadIdx.x;
    const int lane   = t & 31;
    const int worker = t >> 6;          // 0..7 : independent 64-thread worker
    const int ng     = (t >> 5) & 1;    // warp-in-worker : outs [ng*64, ng*64+64)
    const int gid    = lane >> 2;
    const int tig    = lane & 3;
    const int barid  = 1 + worker;

    uint32_t* AhW = (uint32_t*)(smem + OFF_AH) + worker * AWORK;
    uint32_t* AlW = (uint32_t*)(smem + OFF_AL) + worker * AWORK;
    float*    scr = smem + OFF_SCR + worker * 256;   // [0..63] part, [64..159] color partials

    // ---- one-time staging (whole CTA) ----
    for (int idx = t; idx < 4096; idx += NTHREADS) {
        int ln = idx & 31, jn = (idx >> 5) & 15, ks = idx >> 9;
        int n  = jn * 8 + (ln >> 2);
        int k0 = ks * 16 + 2 * (ln & 3);
        float w00 = W2[k0*HID + n],     w01 = W2[(k0+1)*HID + n];
        float w10 = W2[(k0+8)*HID + n], w11 = W2[(k0+9)*HID + n];
        __half2 bh0 = __floats2half2_rn(w00, w01);
        __half2 bh1 = __floats2half2_rn(w10, w11);
        float2 r0 = __half22float2(bh0), r1 = __half22float2(bh1);
        __half2 bl0 = __floats2half2_rn(w00 - r0.x, w01 - r0.y);   // unscaled lo
        __half2 bl1 = __floats2half2_rn(w10 - r1.x, w11 - r1.y);
        Bpk[idx] = make_float4(__uint_as_float(h2u(bh0)), __uint_as_float(h2u(bh1)),
                               __uint_as_float(h2u(bl0)), __uint_as_float(h2u(bl1)));
    }
    if (t < 128) {
        int kseg = t >> 5, klocal = t & 31, kpl = klocal >> 1, hh = klocal & 1;
        ((float4*)(smem + OFF_W1P))[kseg * 34 + kpl * 2 + hh] =
            make_float4(W1[t], W1[HID + t], W1[2*HID + t], b1[t]);
        float* wc1b = smem + OFF_WC1B;
        float* wc2b = smem + OFF_WC2B;
        wc1b[t*4+0] = Wc1[t];       wc1b[t*4+1] = Wc1[HID+t];
        wc1b[t*4+2] = Wc1[2*HID+t]; wc1b[t*4+3] = bc1[t];
        wc2b[t*4+0] = Wc2[3*t];     wc2b[t*4+1] = Wc2[3*t+1];
        wc2b[t*4+2] = Wc2[3*t+2];   wc2b[t*4+3] = 0.0f;
        bw[2*t]   = b2[t];
        bw[2*t+1] = W3[t];
    }
    if (t < 4) (smem + OFF_BC2)[t] = (t < 3) ? bc2[t] : 0.0f;
    const float bias3 = b3[0];
    __syncthreads();                  // only CTA-wide barrier

    const float4* w1p = (const float4*)(smem + OFF_W1P);

    // ldmatrix lane base addresses (worker-local A, mh=0 base)
    const uint32_t ahAddr = sb + (OFF_AH + worker * AWORK) * 4
                          + (uint32_t)(lane & 15) * 272
                          + (uint32_t)((lane >> 4) & 1) * 16;
    const uint32_t alAddr = ahAddr + (OFF_AL - OFF_AH) * 4;

    // B fragment base pointer (this warp's 8 n-groups)
    const float4* bbase = Bpk + ng * 256 + lane;

    const float* bc = smem + OFF_BC2;

    // ---- persistent per-worker tile loop ----
    for (;;) {
        if ((t & 63) == 0) stile[worker] = atomicAdd(&g_tile_ctr, 1);
        BAR_W(barid);
        const int tile = stile[worker];
        if (tile >= ntiles) break;
        const int rbase = tile * TILE_RAYS;

        int ray = rbase + lane;
        if (ray >= N) ray = N - 1;
        float px = org[3*ray], py = org[3*ray + 1], pz = org[3*ray + 2];
        const float dx = dir[3*ray], dy = dir[3*ray + 1], dz = dir[3*ray + 2];
        float dist = 0.f;
        bool hit = false, frozen = false, alldone = false;

        // A0: layer 1 at origins (each warp writes its 64-k half)
        compute_h1(w1p, AhW, AlW, lane, ng, px, py, pz);

        for (int it = 0; it < MAX_IT && !alldone; ++it) {
            BAR_W(barid);             // A writes visible to both warps

            // ===== phase B: single-accumulator 3-term fp16 mma, M32 x N64 =====
            {
                float c[2][8][4];
                #pragma unroll
                for (int mh = 0; mh < 2; ++mh)
                    #pragma unroll
                    for (int j = 0; j < 8; ++j)
                        #pragma unroll
                        for (int q = 0; q < 4; ++q) c[mh][j][q] = 0.f;

                #pragma unroll
                for (int ks = 0; ks < 8; ++ks) {
                    uint32_t ah[2][4], al[2][4];
                    ldsm4(ah[0], ahAddr + ks * 32);
                    ldsm4(ah[1], ahAddr + 4352 + ks * 32);
                    ldsm4(al[0], alAddr + ks * 32);
                    ldsm4(al[1], alAddr + 4352 + ks * 32);
                    #pragma unroll
                    for (int j = 0; j < 8; ++j) {
                        float4 bv = bbase[ks * 512 + j * 32];
                        uint32_t b0h = __float_as_uint(bv.x), b1h = __float_as_uint(bv.y);
                        uint32_t b0l = __float_as_uint(bv.z), b1l = __float_as_uint(bv.w);
                        mma16(c[0][j], ah[0], b0h, b1h);
                        mma16(c[1][j], ah[1], b0h, b1h);
                        mma16(c[0][j], al[0], b0h, b1h);
                        mma16(c[1][j], al[1], b0h, b1h);
                        mma16(c[0][j], ah[0], b0l, b1l);
                        mma16(c[1][j], ah[1], b0l, b1l);
                    }
                }

                // fused layer 3: relu(c + b2) . W3, reduce over n
                float rs[2][2] = {{0.f, 0.f}, {0.f, 0.f}};
                #pragma unroll
                for (int mh = 0; mh < 2; ++mh) {
                    #pragma unroll
                    for (int j = 0; j < 8; ++j) {
                        const int n0 = ng * 64 + j * 8 + tig * 2;
                        float4 bwv = *(const float4*)(bw + n0 * 2);
                        float f0 = c[mh][j][0] + bwv.x;
                        float f1 = c[mh][j][1] + bwv.z;
                        float f2 = c[mh][j][2] + bwv.x;
                        float f3 = c[mh][j][3] + bwv.z;
                        rs[mh][0] = fmaf(fmaxf(f0, 0.f), bwv.y, rs[mh][0]);
                        rs[mh][0] = fmaf(fmaxf(f1, 0.f), bwv.w, rs[mh][0]);
                        rs[mh][1] = fmaf(fmaxf(f2, 0.f), bwv.y, rs[mh][1]);
                        rs[mh][1] = fmaf(fmaxf(f3, 0.f), bwv.w, rs[mh][1]);
                    }
                }
                #pragma unroll
                for (int off = 1; off < 4; off <<= 1) {
                    rs[0][0] += __shfl_xor_sync(0xffffffffu, rs[0][0], off);
                    rs[0][1] += __shfl_xor_sync(0xffffffffu, rs[0][1], off);
                    rs[1][0] += __shfl_xor_sync(0xffffffffu, rs[1][0], off);
                    rs[1][1] += __shfl_xor_sync(0xffffffffu, rs[1][1], off);
                }
                if (tig == 0) {
                    scr[(gid)      * 2 + ng] = rs[0][0];
                    scr[(gid + 8)  * 2 + ng] = rs[0][1];
                    scr[(gid + 16) * 2 + ng] = rs[1][0];
                    scr[(gid + 24) * 2 + ng] = rs[1][1];
                }
            }
            BAR_W(barid);             // part visible

            // ===== phase C: march (state duplicated per warp, identical) =====
            {
                float2 pp = *(const float2*)(scr + lane * 2);
                float sdf = bias3 + pp.x + pp.y;
                if (!frozen) {
                    const bool valid = (sdf <= NEAR_T) && (dist < FAR_T);
                    hit = hit || valid;
                    if (valid) {
                        frozen = true;
                    } else {
                        dist += sdf;
                        px = fmaf(dx, sdf, px);
                        py = fmaf(dy, sdf, py);
                        pz = fmaf(dz, sdf, pz);
                        compute_h1(w1p, AhW, AlW, lane, ng, px, py, pz);
                    }
                }
                unsigned bal = __ballot_sync(0xffffffffu, frozen);
                alldone = (bal == 0xffffffffu);   // identical in both warps
            }
        }

        // ===== color MLP: each warp computes its 64-j half =====
        {
            float c0 = 0.f, c1 = 0.f, c2 = 0.f;
            const float4* wc1b = (const float4*)(smem + OFF_WC1B) + ng * 64;
            const float4* wc2b = (const float4*)(smem + OFF_WC2B) + ng * 64;
            #pragma unroll 4
            for (int j = 0; j < 64; ++j) {
                float4 q  = wc1b[j];
                float4 wv = wc2b[j];
                float h = fmaf(px, q.x, fmaf(py, q.y, fmaf(pz, q.z, q.w)));
                h = fmaxf(h, 0.0f);
                c0 = fmaf(h, wv.x, c0);
                c1 = fmaf(h, wv.y, c1);
                c2 = fmaf(h, wv.z, c2);
            }
            float* cp = scr + 64;
            if (ng == 1) {
                cp[lane * 3 + 0] = c0;
                cp[lane * 3 + 1] = c1;
                cp[lane * 3 + 2] = c2;
            }
            BAR_W(barid);
            if (ng == 0 && (rbase + lane) < N) {
                c0 += cp[lane * 3 + 0] + bc[0];
                c1 += cp[lane * 3 + 1] + bc[1];
                c2 += cp[lane * 3 + 2] + bc[2];
                const bool mask = hit || (dist < FAR_T);
                const int oray = rbase + lane;
                out[3*oray]     = mask ? (1.0f / (1.0f + expf(-c0))) : 0.0f;
                out[3*oray + 1] = mask ? (1.0f / (1.0f + expf(-c1))) : 0.0f;
                out[3*oray + 2] = mask ? (1.0f / (1.0f + expf(-c2))) : 0.0f;
            }
        }
        // loop-top barrier orders scr/A reuse across tiles
    }
}

extern "C" void kernel_launch(void* const* d_in, const int* in_sizes, int n_in,
                              void* d_out, int out_size)
{
    const float* org = (const float*)d_in[0];
    const float* dir = (const float*)d_in[1];
    const float* W1  = (const float*)d_in[2];
    const float* b1  = (const float*)d_in[3];
    const float* W2  = (const float*)d_in[4];
    const float* b2  = (const float*)d_in[5];
    const float* W3  = (const float*)d_in[6];
    const float* b3  = (const float*)d_in[7];
    const float* Wc1 = (const float*)d_in[8];
    const float* bc1 = (const float*)d_in[9];
    const float* Wc2 = (const float*)d_in[10];
    const float* bc2 = (const float*)d_in[11];
    float* out = (float*)d_out;

    const int N = in_sizes[0] / 3;
    const int ntiles = (N + TILE_RAYS - 1) / TILE_RAYS;
    const int smem_bytes = SMEM_WORDS * sizeof(float);

    cudaFuncSetAttribute(sphere_trace_kernel,
                         cudaFuncAttributeMaxDynamicSharedMemorySize, smem_bytes);

    reset_ctr_kernel<<<1, 1>>>();

    int nblocks = 152;                 // 1 persistent CTA/SM, 8 workers of 64 threads
    sphere_trace_kernel<<<nblocks, NTHREADS, smem_bytes>>>(
        org, dir, W1, b1, W2, b2, W3, b3, Wc1, bc1, Wc2, bc2, out, N, ntiles);
}

// round 15
// speedup vs baseline: 1.2367x; 1.0274x over previous
#include <cuda_runtime.h>
#include <cuda_fp16.h>
#include <cstdint>
#include <math.h>

#define HID 128
#define NEAR_T 0.01f
#define FAR_T 10.0f
#define MAX_IT 32
#define NTHREADS 512
#define ASTRIDE 68
#define AWORK 2176          // words per worker A buffer (32*68)
#define RTHRESH 8           // pending lanes before a refill batch

// lane modes
#define M_MARCH 0
#define M_PEND  1
#define M_INACT 2

// ---- smem layout (float-word offsets) ----
#define OFF_BPK   0        // 16384 : B frags float4 (b0h,b1h,b0l,b1l)
#define OFF_AH    16384    // 17408 : Ah, 8 workers x 2176 words
#define OFF_AL    33792    // 17408 : Al (unscaled residual)
#define OFF_W1P   51200    // 544 : W1 interleaved, 4 kseg blocks
#define OFF_WC1B  51744    // 512
#define OFF_WC2B  52256    // 512
#define OFF_BW    52768    // 256 : (b2[n], W3[n])
#define OFF_BC2   53024    // 4
#define OFF_SCR   53028    // 2048 : 8 workers x 256 (part@0, color@64, asn@160)
#define OFF_TILE  55076    // 8 ints
#define SMEM_WORDS 55088   // 220352 bytes -> 1 CTA/SM

__device__ int g_tile_ctr;
__global__ void reset_ctr_kernel() { g_tile_ctr = 0; }

#define BAR_W(id) asm volatile("bar.sync %0, 64;" :: "r"(id) : "memory")

__device__ __forceinline__ uint32_t h2u(__half2 h) {
    return *reinterpret_cast<uint32_t*>(&h);
}
__device__ __forceinline__ uint32_t smem_u32(const void* p) {
    uint32_t a;
    asm("{ .reg .u64 t; cvta.to.shared.u64 t, %1; cvt.u32.u64 %0, t; }" : "=r"(a) : "l"(p));
    return a;
}
__device__ __forceinline__ void mma16(float* c, const uint32_t* a,
                                      uint32_t b0, uint32_t b1) {
    asm volatile(
        "mma.sync.aligned.m16n8k16.row.col.f32.f16.f16.f32 "
        "{%0,%1,%2,%3}, {%4,%5,%6,%7}, {%8,%9}, {%0,%1,%2,%3};"
        : "+f"(c[0]), "+f"(c[1]), "+f"(c[2]), "+f"(c[3])
        : "r"(a[0]), "r"(a[1]), "r"(a[2]), "r"(a[3]), "r"(b0), "r"(b1));
}
__device__ __forceinline__ void ldsm4(uint32_t* r, uint32_t addr) {
    asm volatile("ldmatrix.sync.aligned.m8n8.x4.shared.b16 {%0,%1,%2,%3}, [%4];"
        : "=r"(r[0]), "=r"(r[1]), "=r"(r[2]), "=r"(r[3]) : "r"(addr));
}

// layer 1 for one ray, 64 k (2 ksegs selected by ng), fp16 hi + unscaled lo
__device__ __forceinline__ void compute_h1(const float4* w1p, uint32_t* AhW, uint32_t* AlW,
                                           int ray, int ng,
                                           float px, float py, float pz)
{
    #pragma unroll
    for (int seg = 0; seg < 2; ++seg) {
        const float4* blk = w1p + (2 * ng + seg) * 34;
        #pragma unroll
        for (int j = 0; j < 4; ++j) {
            uint32_t hw[4], lw[4];
            #pragma unroll
            for (int q = 0; q < 4; ++q) {
                int kpl = j * 4 + q;
                float4 q0 = blk[kpl * 2], q1 = blk[kpl * 2 + 1];
                float h0 = fmaxf(fmaf(px, q0.x, fmaf(py, q0.y, fmaf(pz, q0.z, q0.w))), 0.f);
                float h1v = fmaxf(fmaf(px, q1.x, fmaf(py, q1.y, fmaf(pz, q1.z, q1.w))), 0.f);
                __half2 hh = __floats2half2_rn(h0, h1v);
                float2 bk = __half22float2(hh);
                __half2 ll = __floats2half2_rn(h0 - bk.x, h1v - bk.y);
                hw[q] = h2u(hh);
                lw[q] = h2u(ll);
            }
            int base = ray * ASTRIDE + (2 * ng + seg) * 16 + j * 4;
            *(uint4*)(AhW + base) = make_uint4(hw[0], hw[1], hw[2], hw[3]);
            *(uint4*)(AlW + base) = make_uint4(lw[0], lw[1], lw[2], lw[3]);
        }
    }
}

extern __shared__ float smem[];

__global__ void __launch_bounds__(NTHREADS, 1)
sphere_trace_kernel(const float* __restrict__ org,
                    const float* __restrict__ dir,
                    const float* __restrict__ W1, const float* __restrict__ b1,
                    const float* __restrict__ W2, const float* __restrict__ b2,
                    const float* __restrict__ W3, const float* __restrict__ b3,
                    const float* __restrict__ Wc1, const float* __restrict__ bc1,
                    const float* __restrict__ Wc2, const float* __restrict__ bc2,
                    float* __restrict__ out, int N)
{
    float4* Bpk = (float4*)(smem + OFF_BPK);
    float*  bw  = smem + OFF_BW;
    int*    stile = (int*)(smem + OFF_TILE);

    const uint32_t sb = smem_u32(smem);
    const int t      = threadIdx.x;
    const int lane   = t & 31;
    const int worker = t >> 6;          // 0..7 : independent 64-thread worker
    const int ng     = (t >> 5) & 1;    // warp-in-worker : outs [ng*64, ng*64+64)
    const int gid    = lane >> 2;
    const int tig    = lane & 3;
    const int barid  = 1 + worker;

    uint32_t* AhW = (uint32_t*)(smem + OFF_AH) + worker * AWORK;
    uint32_t* AlW = (uint32_t*)(smem + OFF_AL) + worker * AWORK;
    float*    scr = smem + OFF_SCR + worker * 256;  // part@0, color@64, asn@160
    float*    cp  = scr + 64;
    int*      asn = (int*)(scr + 160);

    // ---- one-time staging (whole CTA) ----
    for (int idx = t; idx < 4096; idx += NTHREADS) {
        int ln = idx & 31, jn = (idx >> 5) & 15, ks = idx >> 9;
        int n  = jn * 8 + (ln >> 2);
        int k0 = ks * 16 + 2 * (ln & 3);
        float w00 = W2[k0*HID + n],     w01 = W2[(k0+1)*HID + n];
        float w10 = W2[(k0+8)*HID + n], w11 = W2[(k0+9)*HID + n];
        __half2 bh0 = __floats2half2_rn(w00, w01);
        __half2 bh1 = __floats2half2_rn(w10, w11);
        float2 r0 = __half22float2(bh0), r1 = __half22float2(bh1);
        __half2 bl0 = __floats2half2_rn(w00 - r0.x, w01 - r0.y);
        __half2 bl1 = __floats2half2_rn(w10 - r1.x, w11 - r1.y);
        Bpk[idx] = make_float4(__uint_as_float(h2u(bh0)), __uint_as_float(h2u(bh1)),
                               __uint_as_float(h2u(bl0)), __uint_as_float(h2u(bl1)));
    }
    if (t < 128) {
        int kseg = t >> 5, klocal = t & 31, kpl = klocal >> 1, hh = klocal & 1;
        ((float4*)(smem + OFF_W1P))[kseg * 34 + kpl * 2 + hh] =
            make_float4(W1[t], W1[HID + t], W1[2*HID + t], b1[t]);
        float* wc1b = smem + OFF_WC1B;
        float* wc2b = smem + OFF_WC2B;
        wc1b[t*4+0] = Wc1[t];       wc1b[t*4+1] = Wc1[HID+t];
        wc1b[t*4+2] = Wc1[2*HID+t]; wc1b[t*4+3] = bc1[t];
        wc2b[t*4+0] = Wc2[3*t];     wc2b[t*4+1] = Wc2[3*t+1];
        wc2b[t*4+2] = Wc2[3*t+2];   wc2b[t*4+3] = 0.0f;
        bw[2*t]   = b2[t];
        bw[2*t+1] = W3[t];
    }
    if (t < 4) (smem + OFF_BC2)[t] = (t < 3) ? bc2[t] : 0.0f;
    const float bias3 = b3[0];
    __syncthreads();                  // only CTA-wide barrier

    const float4* w1p = (const float4*)(smem + OFF_W1P);

    const uint32_t ahAddr = sb + (OFF_AH + worker * AWORK) * 4
                          + (uint32_t)(lane & 15) * 272
                          + (uint32_t)((lane >> 4) & 1) * 16;
    const uint32_t alAddr = ahAddr + (OFF_AL - OFF_AH) * 4;
    const float4* bbase = Bpk + ng * 256 + lane;
    const float* bc = smem + OFF_BC2;

    // ---- initial ray grab: 32 rays per worker ----
    if ((t & 63) == 0) stile[worker] = atomicAdd(&g_tile_ctr, 32);
    BAR_W(barid);
    int myray = stile[worker] + lane;
    int mode = (myray < N) ? M_MARCH : M_INACT;

    float px = 0.f, py = 0.f, pz = 0.f, dx = 0.f, dy = 0.f, dz = 0.f;
    float dist = 0.f;
    bool hit = false;
    int it = 0;
    if (mode == M_MARCH) {
        px = org[3*myray]; py = org[3*myray+1]; pz = org[3*myray+2];
        dx = dir[3*myray]; dy = dir[3*myray+1]; dz = dir[3*myray+2];
        compute_h1(w1p, AhW, AlW, lane, ng, px, py, pz);
    }

    // ---- persistent per-lane march loop ----
    for (;;) {
        unsigned balM = __ballot_sync(0xffffffffu, mode == M_MARCH);
        unsigned balP = __ballot_sync(0xffffffffu, mode == M_PEND);
        if (!(balM | balP)) break;
        const bool doB = (balM != 0);
        const bool doR = (__popc(balP) >= RTHRESH) || !doB;

        if (doB) {
            BAR_W(barid);             // A writes visible

            // ===== phase B: single-accumulator 3-term fp16 mma, M32 x N64 =====
            {
                float c[2][8][4];
                #pragma unroll
                for (int mh = 0; mh < 2; ++mh)
                    #pragma unroll
                    for (int j = 0; j < 8; ++j)
                        #pragma unroll
                        for (int q = 0; q < 4; ++q) c[mh][j][q] = 0.f;

                #pragma unroll
                for (int ks = 0; ks < 8; ++ks) {
                    uint32_t ah[2][4], al[2][4];
                    ldsm4(ah[0], ahAddr + ks * 32);
                    ldsm4(ah[1], ahAddr + 4352 + ks * 32);
                    ldsm4(al[0], alAddr + ks * 32);
                    ldsm4(al[1], alAddr + 4352 + ks * 32);
                    #pragma unroll
                    for (int j = 0; j < 8; ++j) {
                        float4 bv = bbase[ks * 512 + j * 32];
                        uint32_t b0h = __float_as_uint(bv.x), b1h = __float_as_uint(bv.y);
                        uint32_t b0l = __float_as_uint(bv.z), b1l = __float_as_uint(bv.w);
                        mma16(c[0][j], ah[0], b0h, b1h);
                        mma16(c[1][j], ah[1], b0h, b1h);
                        mma16(c[0][j], al[0], b0h, b1h);
                        mma16(c[1][j], al[1], b0h, b1h);
                        mma16(c[0][j], ah[0], b0l, b1l);
                        mma16(c[1][j], ah[1], b0l, b1l);
                    }
                }

                float rs[2][2] = {{0.f, 0.f}, {0.f, 0.f}};
                #pragma unroll
                for (int mh = 0; mh < 2; ++mh) {
                    #pragma unroll
                    for (int j = 0; j < 8; ++j) {
                        const int n0 = ng * 64 + j * 8 + tig * 2;
                        float4 bwv = *(const float4*)(bw + n0 * 2);
                        float f0 = c[mh][j][0] + bwv.x;
                        float f1 = c[mh][j][1] + bwv.z;
                        float f2 = c[mh][j][2] + bwv.x;
                        float f3 = c[mh][j][3] + bwv.z;
                        rs[mh][0] = fmaf(fmaxf(f0, 0.f), bwv.y, rs[mh][0]);
                        rs[mh][0] = fmaf(fmaxf(f1, 0.f), bwv.w, rs[mh][0]);
                        rs[mh][1] = fmaf(fmaxf(f2, 0.f), bwv.y, rs[mh][1]);
                        rs[mh][1] = fmaf(fmaxf(f3, 0.f), bwv.w, rs[mh][1]);
                    }
                }
                #pragma unroll
                for (int off = 1; off < 4; off <<= 1) {
                    rs[0][0] += __shfl_xor_sync(0xffffffffu, rs[0][0], off);
                    rs[0][1] += __shfl_xor_sync(0xffffffffu, rs[0][1], off);
                    rs[1][0] += __shfl_xor_sync(0xffffffffu, rs[1][0], off);
                    rs[1][1] += __shfl_xor_sync(0xffffffffu, rs[1][1], off);
                }
                if (tig == 0) {
                    scr[(gid)      * 2 + ng] = rs[0][0];
                    scr[(gid + 8)  * 2 + ng] = rs[0][1];
                    scr[(gid + 16) * 2 + ng] = rs[1][0];
                    scr[(gid + 24) * 2 + ng] = rs[1][1];
                }
            }
            BAR_W(barid);             // part visible

            // ===== phase C: march (state mirrored identically in both warps) =====
            if (mode == M_MARCH) {
                float2 pp = *(const float2*)(scr + lane * 2);
                float sdf = bias3 + pp.x + pp.y;
                const bool valid = (sdf <= NEAR_T) && (dist < FAR_T);
                hit = hit || valid;
                if (valid) {
                    mode = M_PEND;
                } else {
                    dist += sdf;
                    px = fmaf(dx, sdf, px);
                    py = fmaf(dy, sdf, py);
                    pz = fmaf(dz, sdf, pz);
                    if (++it >= MAX_IT) mode = M_PEND;
                    else compute_h1(w1p, AhW, AlW, lane, ng, px, py, pz);
                }
            }
        }

        if (doR) {
            // color MLP: each warp computes its 64-j half for its lane's ray
            float c0 = 0.f, c1 = 0.f, c2 = 0.f;
            {
                const float4* wc1b = (const float4*)(smem + OFF_WC1B) + ng * 64;
                const float4* wc2b = (const float4*)(smem + OFF_WC2B) + ng * 64;
                #pragma unroll 4
                for (int j = 0; j < 64; ++j) {
                    float4 q  = wc1b[j];
                    float4 wv = wc2b[j];
                    float h = fmaf(px, q.x, fmaf(py, q.y, fmaf(pz, q.z, q.w)));
                    h = fmaxf(h, 0.0f);
                    c0 = fmaf(h, wv.x, c0);
                    c1 = fmaf(h, wv.y, c1);
                    c2 = fmaf(h, wv.z, c2);
                }
            }
            if (ng == 1) {
                cp[lane * 3 + 0] = c0;
                cp[lane * 3 + 1] = c1;
                cp[lane * 3 + 2] = c2;
            }
            unsigned balP2 = __ballot_sync(0xffffffffu, mode == M_PEND);
            if (ng == 0) {
                int cnt = __popc(balP2);
                int base = 0;
                if (lane == 0 && cnt) base = atomicAdd(&g_tile_ctr, cnt);
                base = __shfl_sync(0xffffffffu, base, 0);
                if (mode == M_PEND)
                    asn[lane] = base + __popc(balP2 & ((1u << lane) - 1u));
            }
            BAR_W(barid);             // cp + asn visible
            if (mode == M_PEND) {
                if (ng == 0) {
                    const bool mask = hit || (dist < FAR_T);
                    float o0 = c0 + cp[lane * 3 + 0] + bc[0];
                    float o1 = c1 + cp[lane * 3 + 1] + bc[1];
                    float o2 = c2 + cp[lane * 3 + 2] + bc[2];
                    out[3*myray]     = mask ? (1.0f / (1.0f + expf(-o0))) : 0.0f;
                    out[3*myray + 1] = mask ? (1.0f / (1.0f + expf(-o1))) : 0.0f;
                    out[3*myray + 2] = mask ? (1.0f / (1.0f + expf(-o2))) : 0.0f;
                }
                int nr = asn[lane];
                if (nr < N) {
                    myray = nr;
                    px = org[3*nr]; py = org[3*nr+1]; pz = org[3*nr+2];
                    dx = dir[3*nr]; dy = dir[3*nr+1]; dz = dir[3*nr+2];
                    dist = 0.f; hit = false; it = 0;
                    mode = M_MARCH;
                    compute_h1(w1p, AhW, AlW, lane, ng, px, py, pz);
                } else {
                    mode = M_INACT;
                }
            }
        }
    }
}

extern "C" void kernel_launch(void* const* d_in, const int* in_sizes, int n_in,
                              void* d_out, int out_size)
{
    const float* org = (const float*)d_in[0];
    const float* dir = (const float*)d_in[1];
    const float* W1  = (const float*)d_in[2];
    const float* b1  = (const float*)d_in[3];
    const float* W2  = (const float*)d_in[4];
    const float* b2  = (const float*)d_in[5];
    const float* W3  = (const float*)d_in[6];
    const float* b3  = (const float*)d_in[7];
    const float* Wc1 = (const float*)d_in[8];
    const float* bc1 = (const float*)d_in[9];
    const float* Wc2 = (const float*)d_in[10];
    const float* bc2 = (const float*)d_in[11];
    float* out = (float*)d_out;

    const int N = in_sizes[0] / 3;
    const int smem_bytes = SMEM_WORDS * sizeof(float);

    cudaFuncSetAttribute(sphere_trace_kernel,
                         cudaFuncAttributeMaxDynamicSharedMemorySize, smem_bytes);

    reset_ctr_kernel<<<1, 1>>>();

    int nblocks = 152;                 // 1 persistent CTA/SM, 8 workers of 64 threads
    sphere_trace_kernel<<<nblocks, NTHREADS, smem_bytes>>>(
        org, dir, W1, b1, W2, b2, W3, b3, Wc1, bc1, Wc2, bc2, out, N);
}